// round 14
// baseline (speedup 1.0000x reference)
#include <cuda_runtime.h>
#include <cstdint>

// ResidualGraphConv via Horner over combined channels Wc[d] = [W1[d]; W2[d]]:
//   V = U3;  V = V*A + U2;  V = V*A + U1;  out = V*A + U0 (+bias, relu upper 32)
// with U_d = Wc[d] @ x fused as two trailing K=32 chunks of each GEMM.
//
// mma.sync.m16n8k8 tf32. tf32 RNA rounding applied at gather (adj/x/W) and at
// V-producer epilogue (bit-identical to consumer-side rounding of prior rounds).
// Fragment-major SMEM: fragments load as LDS.128/LDS.64, conflict-free.
// Double-buffered SMEM, reg staging, 1 sync/chunk, 2-chunk LDG lookahead.

#define BATCH 16
#define CCH   64
#define NN    2048
#define NT    64
#define KB    32
#define A_FL  2048            // 16 blocks (kk*4+mt) * 128 floats
#define B_FL  2048            // 32 blocks (kk*8+jn) * 64 floats
#define STAGE_FL (A_FL + B_FL)

__device__ float g_V0[BATCH * CCH * NN];
__device__ float g_V1[BATCH * CCH * NN];

__device__ __forceinline__ uint32_t ftf32(float v) {
    uint32_t u;
    asm("cvt.rna.tf32.f32 %0, %1;" : "=r"(u) : "f"(v));
    return u;
}
__device__ __forceinline__ float ftf32f(float v) {
    return __uint_as_float(ftf32(v));
}

__device__ __forceinline__ void mma_tf32(float* c, const uint32_t* a, const uint32_t* bb) {
    asm volatile(
        "mma.sync.aligned.m16n8k8.row.col.f32.tf32.tf32.f32 "
        "{%0,%1,%2,%3}, {%4,%5,%6,%7}, {%8,%9}, {%0,%1,%2,%3};\n"
        : "+f"(c[0]), "+f"(c[1]), "+f"(c[2]), "+f"(c[3])
        : "r"(a[0]), "r"(a[1]), "r"(a[2]), "r"(a[3]), "r"(bb[0]), "r"(bb[1]));
}

// vin_sel: 0 -> g_V0, 1 -> g_V1. vout_sel: 0 -> g_V0 (tf32-rounded),
// 1 -> g_V1 (tf32-rounded), 2 -> dout (full f32, +bias, relu upper half)
__global__ void __launch_bounds__(256, 3)
horner_kernel(const float* __restrict__ adj,
              const float* __restrict__ x,
              const float* __restrict__ W1,
              const float* __restrict__ W2,
              const float* __restrict__ bias1,
              const float* __restrict__ bias2,
              float* __restrict__ dout,
              int nk_main, int deg, int vin_sel, int vout_sel) {
    __shared__ float sm[2 * STAGE_FL];   // 32 KB, double buffered

    const int tid  = threadIdx.x;
    const int lane = tid & 31;
    const int wid  = tid >> 5;           // 0..7
    const int wm   = wid >> 2;           // 0..1 : m-half (mtiles 2wm, 2wm+1)
    const int wn   = wid & 3;            // 0..3 : n-quarter (jn 2wn, 2wn+1)
    const int g    = lane >> 2;          // 0..7
    const int t    = lane & 3;           // 0..3
    const int b    = blockIdx.y;
    const int m0   = blockIdx.x * NT;

    const float* Vin  = vin_sel ? g_V1 : g_V0;
    float*       Vout = (vout_sel == 0) ? g_V0 : ((vout_sel == 1) ? g_V1 : dout);

    const int nchunks = nk_main + 2;

    // ---- gather registers (one chunk) ----
    uint32_t aG[2][4];   // A blocks wid, wid+8  (blk = kk*4+mt)
    uint32_t bG[4][2];   // B blocks i*8+wid, i=0..3 (blk = kk*8+jn, jn = wid)

    // A gather: fragment element (blk, lane, comp):
    //   kk = blk>>2, mt = blk&3; row = mt*16 + g + (comp&1)*8; col = kk*8 + t + (comp>>1)*4
    auto gatherA = [&](int cc) {
        const bool isU = (cc >= nk_main);
        const int  k0  = cc * KB;
        const int  ci0 = (cc - nk_main) * KB;
#pragma unroll
        for (int ib = 0; ib < 2; ib++) {
            const int blk = wid + ib * 8;
            const int kk  = blk >> 2;
            const int mt  = blk & 3;
#pragma unroll
            for (int cmp = 0; cmp < 4; cmp++) {
                const int r = mt * 16 + g + (cmp & 1) * 8;
                const int c = kk * 8 + t + (cmp >> 1) * 4;
                float v;
                if (!isU) {
                    v = Vin[((b << 6) + r) * NN + k0 + c];
                } else {
                    const float* W = (r < 32) ? W1 : W2;
                    v = W[((deg * 32 + (r & 31)) << 6) + ci0 + c];
                }
                aG[ib][cmp] = ftf32(v);
            }
        }
    };

    // B gather: fragment element (kk=i, jn=wid, lane, comp):
    //   k = i*8 + t + comp*4; col = m0 + wid*8 + g
    auto gatherB = [&](int cc) {
        const bool isU = (cc >= nk_main);
        const int  k0  = cc * KB;
        const int  ci0 = (cc - nk_main) * KB;
        const int  col = m0 + wid * 8 + g;
#pragma unroll
        for (int i = 0; i < 4; i++) {
#pragma unroll
            for (int cmp = 0; cmp < 2; cmp++) {
                const int k = i * 8 + t + cmp * 4;
                float v;
                if (!isU) {
                    v = adj[(size_t)(b * NN + k0 + k) * NN + col];
                } else {
                    v = x[((b << 6) + ci0 + k) * NN + col];
                }
                bG[i][cmp] = ftf32(v);
            }
        }
    };

    auto sts = [&](int stage) {
        float* S  = sm + stage * STAGE_FL;
        float* SB = S + A_FL;
        // A: block = 128 floats = 32 lanes * float4 (contiguous per warp)
        *reinterpret_cast<uint4*>(S + (wid)     * 128 + lane * 4) =
            make_uint4(aG[0][0], aG[0][1], aG[0][2], aG[0][3]);
        *reinterpret_cast<uint4*>(S + (wid + 8) * 128 + lane * 4) =
            make_uint4(aG[1][0], aG[1][1], aG[1][2], aG[1][3]);
        // B: block = 64 floats = 32 lanes * float2
#pragma unroll
        for (int i = 0; i < 4; i++) {
            *reinterpret_cast<uint2*>(SB + (i * 8 + wid) * 64 + lane * 2) =
                make_uint2(bG[i][0], bG[i][1]);
        }
    };

    float acc[2][2][4];
#pragma unroll
    for (int i = 0; i < 2; i++)
#pragma unroll
        for (int j = 0; j < 2; j++)
#pragma unroll
            for (int q = 0; q < 4; q++) acc[i][j][q] = 0.0f;

    // ---- prologue ----
    gatherA(0); gatherB(0);
    sts(0);
    if (nchunks > 1) { gatherA(1); gatherB(1); }
    __syncthreads();

    for (int cc = 0; cc < nchunks; cc++) {
        if (cc + 1 < nchunks) sts((cc + 1) & 1);              // regs(cc+1) -> buf
        if (cc + 2 < nchunks) { gatherA(cc + 2); gatherB(cc + 2); }  // LDG lookahead

        const float* S  = sm + (cc & 1) * STAGE_FL;
        const float* SB = S + A_FL;
#pragma unroll
        for (int kk = 0; kk < 4; kk++) {
            uint4 a0 = *reinterpret_cast<const uint4*>(S + (kk * 4 + 2 * wm)     * 128 + lane * 4);
            uint4 a1 = *reinterpret_cast<const uint4*>(S + (kk * 4 + 2 * wm + 1) * 128 + lane * 4);
            uint2 b0 = *reinterpret_cast<const uint2*>(SB + (kk * 8 + 2 * wn)     * 64 + lane * 2);
            uint2 b1 = *reinterpret_cast<const uint2*>(SB + (kk * 8 + 2 * wn + 1) * 64 + lane * 2);
            mma_tf32(acc[0][0], &a0.x, &b0.x);
            mma_tf32(acc[0][1], &a0.x, &b1.x);
            mma_tf32(acc[1][0], &a1.x, &b0.x);
            mma_tf32(acc[1][1], &a1.x, &b1.x);
        }
        __syncthreads();
    }

    // ---- epilogue ----
#pragma unroll
    for (int i = 0; i < 2; i++) {
        const int r0 = (2 * wm + i) * 16 + g;
        const int r1 = r0 + 8;
        float add0 = 0.0f, add1 = 0.0f;
        bool relu = false;
        if (vout_sel == 2) {
            add0 = (r0 < 32) ? bias1[r0] : bias2[r0 - 32];
            add1 = (r1 < 32) ? bias1[r1] : bias2[r1 - 32];
            relu = (r0 >= 32);   // uniform per (wm,i): wm=1 rows are 32..63
        }
#pragma unroll
        for (int j = 0; j < 2; j++) {
            const int m = m0 + (2 * wn + j) * 8 + 2 * t;
            float v0 = acc[i][j][0], v1 = acc[i][j][1];   // row r0
            float v2 = acc[i][j][2], v3 = acc[i][j][3];   // row r1
            if (vout_sel == 2) {
                v0 += add0; v1 += add0;
                v2 += add1; v3 += add1;
                if (relu) {
                    v0 = fmaxf(v0, 0.0f); v1 = fmaxf(v1, 0.0f);
                    v2 = fmaxf(v2, 0.0f); v3 = fmaxf(v3, 0.0f);
                }
            } else {
                // round V at the producer: bit-identical to consumer-side rounding
                v0 = ftf32f(v0); v1 = ftf32f(v1);
                v2 = ftf32f(v2); v3 = ftf32f(v3);
            }
            *reinterpret_cast<float2*>(&Vout[((b << 6) + r0) * NN + m]) = make_float2(v0, v1);
            *reinterpret_cast<float2*>(&Vout[((b << 6) + r1) * NN + m]) = make_float2(v2, v3);
        }
    }
}

extern "C" void kernel_launch(void* const* d_in, const int* in_sizes, int n_in,
                              void* d_out, int out_size) {
    (void)in_sizes; (void)n_in; (void)out_size;
    const float* adj = (const float*)d_in[0];   // [16,2048,2048]
    const float* x   = (const float*)d_in[1];   // [16,64,2048]
    const float* W1  = (const float*)d_in[2];   // [4,32,64]
    const float* b1  = (const float*)d_in[3];   // [32]
    const float* W2  = (const float*)d_in[4];   // [4,32,64]
    const float* b2  = (const float*)d_in[5];   // [32]
    float* out = (float*)d_out;                 // [16,64,2048]

    dim3 grid(NN / NT, BATCH);   // 32 x 16 = 512 CTAs
    dim3 block(256);

    // V0 = U3 (projection only)
    horner_kernel<<<grid, block>>>(adj, x, W1, W2, b1, b2, out, 0, 3, 0, 0);
    // V1 = V0*A + U2
    horner_kernel<<<grid, block>>>(adj, x, W1, W2, b1, b2, out, NN / KB, 2, 0, 1);
    // V0 = V1*A + U1
    horner_kernel<<<grid, block>>>(adj, x, W1, W2, b1, b2, out, NN / KB, 1, 1, 0);
    // out = V0*A + U0 + bias, relu upper half
    horner_kernel<<<grid, block>>>(adj, x, W1, W2, b1, b2, out, NN / KB, 0, 0, 2);
}

// round 15
// speedup vs baseline: 3.0315x; 3.0315x over previous
#include <cuda_runtime.h>
#include <cstdint>

// ResidualGraphConv via Horner over combined channels Wc[d] = [W1[d]; W2[d]]:
//   V = U3;  V = V*A + U2;  V = V*A + U1;  out = V*A + U0 (+bias, relu upper 32)
// with U_d = Wc[d] @ x fused as two trailing K=32 chunks of each GEMM.
//
// mma.sync.m16n8k8 tf32. V is tf32-RNA-rounded at the producer epilogue, so
// the A operand needs NO cvt in the main loop (HW truncation is identity).
// adj/x/W are cvt.rna'd at fragment load. cp.async 3-stage pipeline,
// CTA tile 64x64, 128 threads, warp tile 32x32, grid 512 = single wave @ occ 4.

#define BATCH 16
#define CCH   64
#define NN    2048
#define NT    64
#define KB    32
#define LDA   36                        // 32 data + 4 pad floats
#define LDB   72                        // 64 data + 8 pad floats
#define A_FL  (CCH * LDA)               // 2304 floats
#define B_FL  (KB * LDB)                // 2304 floats
#define STAGE_FL (A_FL + B_FL)          // 4608 floats = 18432 B
#define STAGES 3
#define SMEM_BYTES (STAGES * STAGE_FL * 4)   // 55296 B

__device__ float g_V0[BATCH * CCH * NN];
__device__ float g_V1[BATCH * CCH * NN];

__device__ __forceinline__ uint32_t ftf32(float v) {
    uint32_t u;
    asm("cvt.rna.tf32.f32 %0, %1;" : "=r"(u) : "f"(v));
    return u;
}
__device__ __forceinline__ float ftf32f(float v) { return __uint_as_float(ftf32(v)); }

__device__ __forceinline__ void cp_async16(uint32_t smem_addr, const float* gptr) {
    asm volatile("cp.async.cg.shared.global [%0], [%1], 16;\n"
                 :: "r"(smem_addr), "l"(gptr));
}
__device__ __forceinline__ void cp_commit() {
    asm volatile("cp.async.commit_group;\n" ::: "memory");
}
__device__ __forceinline__ void cp_wait1() {
    asm volatile("cp.async.wait_group 1;\n" ::: "memory");
}

__device__ __forceinline__ void mma_tf32(float* c, const uint32_t* a, const uint32_t* bb) {
    asm volatile(
        "mma.sync.aligned.m16n8k8.row.col.f32.tf32.tf32.f32 "
        "{%0,%1,%2,%3}, {%4,%5,%6,%7}, {%8,%9}, {%0,%1,%2,%3};\n"
        : "+f"(c[0]), "+f"(c[1]), "+f"(c[2]), "+f"(c[3])
        : "r"(a[0]), "r"(a[1]), "r"(a[2]), "r"(a[3]), "r"(bb[0]), "r"(bb[1]));
}

// vin_sel: 0 -> g_V0, 1 -> g_V1. vout_sel: 0 -> g_V0 (tf32-rounded),
// 1 -> g_V1 (tf32-rounded), 2 -> dout (full f32, +bias, relu upper half)
__global__ void __launch_bounds__(128, 4)
horner_kernel(const float* __restrict__ adj,
              const float* __restrict__ x,
              const float* __restrict__ W1,
              const float* __restrict__ W2,
              const float* __restrict__ bias1,
              const float* __restrict__ bias2,
              float* __restrict__ dout,
              int nk_main, int deg, int vin_sel, int vout_sel) {
    extern __shared__ float sm[];

    const int tid  = threadIdx.x;          // 0..127
    const int lane = tid & 31;
    const int wid  = tid >> 5;             // 0..3
    const int wm   = wid & 1;              // m-half: rows wm*32..+31
    const int wn   = wid >> 1;             // n-half: cols wn*32..+31
    const int g    = lane >> 2;            // 0..7
    const int t    = lane & 3;             // 0..3
    const int b    = blockIdx.y;
    const int m0   = blockIdx.x * NT;

    const float* Vin  = vin_sel ? g_V1 : g_V0;
    float*       Vout = (vout_sel == 0) ? g_V0 : ((vout_sel == 1) ? g_V1 : dout);

    const int nchunks = nk_main + 2;

    const uint32_t smbase = (uint32_t)__cvta_generic_to_shared(sm);

    // ---- staging: 8 cp.async.16 per thread per chunk, fully coalesced ----
    auto load_chunk = [&](int cc, int stage) {
        if (cc < nchunks) {
            const bool isU = (cc >= nk_main);
            const int  k0  = cc * KB;
            const int  ci0 = (cc - nk_main) * KB;
            const uint32_t sA = smbase + (uint32_t)(stage * STAGE_FL) * 4u;
            const uint32_t sB = sA + (uint32_t)A_FL * 4u;
            // A: 64 rows x 32 floats = 512 float4 slots; li = i*128+tid -> warp covers 512B runs
#pragma unroll
            for (int i = 0; i < 4; i++) {
                const int li  = i * 128 + tid;
                const int row = li >> 3;
                const int q   = li & 7;
                const float* src;
                if (!isU) {
                    src = Vin + ((b << 6) + row) * NN + k0 + (q << 2);
                } else {
                    const float* W = (row < 32) ? W1 : W2;
                    src = W + ((deg * 32 + (row & 31)) << 6) + ci0 + (q << 2);
                }
                cp_async16(sA + (uint32_t)(row * LDA + (q << 2)) * 4u, src);
            }
            // B: 32 k-rows x 64 floats = 512 float4 slots
#pragma unroll
            for (int i = 0; i < 4; i++) {
                const int li = i * 128 + tid;
                const int kr = li >> 4;
                const int q  = li & 15;
                const float* src;
                if (!isU) {
                    src = adj + (size_t)(b * NN + k0 + kr) * NN + m0 + (q << 2);
                } else {
                    src = x + ((b << 6) + ci0 + kr) * NN + m0 + (q << 2);
                }
                cp_async16(sB + (uint32_t)(kr * LDB + (q << 2)) * 4u, src);
            }
        }
        cp_commit();   // always commit to keep group counting uniform
    };

    float acc[2][4][4];
#pragma unroll
    for (int mt = 0; mt < 2; mt++)
#pragma unroll
        for (int jn = 0; jn < 4; jn++)
#pragma unroll
            for (int q = 0; q < 4; q++) acc[mt][jn][q] = 0.0f;

    // ---- prologue ----
    load_chunk(0, 0);
    load_chunk(1, 1);

    for (int cc = 0; cc < nchunks; cc++) {
        cp_wait1();            // chunk cc landed (cc+1 may still be in flight)
        __syncthreads();       // visibility + all warps done with stage (cc-1)%3

        load_chunk(cc + 2, (cc + 2) % STAGES);

        const float* S  = sm + (cc % STAGES) * STAGE_FL;
        const float* SB = S + A_FL;
        const bool   isU = (cc >= nk_main);   // uniform branch per chunk

#pragma unroll
        for (int kk = 0; kk < 4; kk++) {
            const int kb = kk * 8;
            uint32_t a[2][4];
#pragma unroll
            for (int mt = 0; mt < 2; mt++) {
                const int base = (wm * 32 + mt * 16 + g) * LDA + kb + t;
                float v0 = S[base];
                float v1 = S[base + 8 * LDA];
                float v2 = S[base + 4];
                float v3 = S[base + 8 * LDA + 4];
                if (isU) {   // W needs RNA rounding; V is pre-rounded (identity)
                    a[mt][0] = ftf32(v0); a[mt][1] = ftf32(v1);
                    a[mt][2] = ftf32(v2); a[mt][3] = ftf32(v3);
                } else {
                    a[mt][0] = __float_as_uint(v0); a[mt][1] = __float_as_uint(v1);
                    a[mt][2] = __float_as_uint(v2); a[mt][3] = __float_as_uint(v3);
                }
            }
#pragma unroll
            for (int jn = 0; jn < 4; jn++) {
                const int col = wn * 32 + jn * 8 + g;
                uint32_t bf[2];
                bf[0] = ftf32(SB[(kb + t) * LDB + col]);
                bf[1] = ftf32(SB[(kb + t + 4) * LDB + col]);
                mma_tf32(acc[0][jn], a[0], bf);
                mma_tf32(acc[1][jn], a[1], bf);
            }
        }
    }

    // ---- epilogue ----
#pragma unroll
    for (int mt = 0; mt < 2; mt++) {
        const int r0 = wm * 32 + mt * 16 + g;
        const int r1 = r0 + 8;
        float add0 = 0.0f, add1 = 0.0f;
        bool relu = false;
        if (vout_sel == 2) {
            add0 = (r0 < 32) ? bias1[r0] : bias2[r0 - 32];
            add1 = (r1 < 32) ? bias1[r1] : bias2[r1 - 32];
            relu = (wm == 1);   // rows 32..63 = nonlinear half (r0,r1 same half)
        }
#pragma unroll
        for (int jn = 0; jn < 4; jn++) {
            const int m = m0 + wn * 32 + jn * 8 + 2 * t;
            float v0 = acc[mt][jn][0], v1 = acc[mt][jn][1];   // row r0
            float v2 = acc[mt][jn][2], v3 = acc[mt][jn][3];   // row r1
            if (vout_sel == 2) {
                v0 += add0; v1 += add0;
                v2 += add1; v3 += add1;
                if (relu) {
                    v0 = fmaxf(v0, 0.0f); v1 = fmaxf(v1, 0.0f);
                    v2 = fmaxf(v2, 0.0f); v3 = fmaxf(v3, 0.0f);
                }
            } else {
                // producer-side tf32 rounding (bit-identical to consumer-side)
                v0 = ftf32f(v0); v1 = ftf32f(v1);
                v2 = ftf32f(v2); v3 = ftf32f(v3);
            }
            *reinterpret_cast<float2*>(&Vout[((b << 6) + r0) * NN + m]) = make_float2(v0, v1);
            *reinterpret_cast<float2*>(&Vout[((b << 6) + r1) * NN + m]) = make_float2(v2, v3);
        }
    }
}

extern "C" void kernel_launch(void* const* d_in, const int* in_sizes, int n_in,
                              void* d_out, int out_size) {
    (void)in_sizes; (void)n_in; (void)out_size;
    const float* adj = (const float*)d_in[0];   // [16,2048,2048]
    const float* x   = (const float*)d_in[1];   // [16,64,2048]
    const float* W1  = (const float*)d_in[2];   // [4,32,64]
    const float* b1  = (const float*)d_in[3];   // [32]
    const float* W2  = (const float*)d_in[4];   // [4,32,64]
    const float* b2  = (const float*)d_in[5];   // [32]
    float* out = (float*)d_out;                 // [16,64,2048]

    static bool attr_set = false;
    if (!attr_set) {
        cudaFuncSetAttribute(horner_kernel,
                             cudaFuncAttributeMaxDynamicSharedMemorySize, SMEM_BYTES);
        attr_set = true;
    }

    dim3 grid(NN / NT, BATCH);   // 32 x 16 = 512 CTAs -> single wave @ 4 CTA/SM
    dim3 block(128);

    // V0 = U3 (projection only)
    horner_kernel<<<grid, block, SMEM_BYTES>>>(adj, x, W1, W2, b1, b2, out, 0, 3, 0, 0);
    // V1 = V0*A + U2
    horner_kernel<<<grid, block, SMEM_BYTES>>>(adj, x, W1, W2, b1, b2, out, NN / KB, 2, 0, 1);
    // V0 = V1*A + U1
    horner_kernel<<<grid, block, SMEM_BYTES>>>(adj, x, W1, W2, b1, b2, out, NN / KB, 1, 1, 0);
    // out = V0*A + U0 + bias, relu upper half
    horner_kernel<<<grid, block, SMEM_BYTES>>>(adj, x, W1, W2, b1, b2, out, NN / KB, 0, 0, 2);
}